// round 16
// baseline (speedup 1.0000x reference)
#include <cuda_runtime.h>
#include <stdint.h>

#define NBINS 29
#define DDIM  4096
#define CDIM  4
#define QDIM  32
#define NWARP 8
#define NSLOT 5          // ring slots per warp (prefetch distance 4)
#define NSLICE 20        // per row: 4 iters x (1 mask + 4 sim) slices
#define RPB   2          // rows per block -> grid 1024 = ONE residency wave

__device__ __forceinline__ void cp_async16_ef(uint32_t saddr, const void* gaddr,
                                              uint64_t pol) {
    asm volatile("cp.async.cg.shared.global.L2::cache_hint [%0], [%1], 16, %2;\n"
                 :: "r"(saddr), "l"(gaddr), "l"(pol) : "memory");
}
#define CP_COMMIT() asm volatile("cp.async.commit_group;\n" ::: "memory")
#define CP_WAIT(N)  asm volatile("cp.async.wait_group %0;\n" :: "n"(N) : "memory")

// R15 (evict_first, 29.06us kernel: the proven policy win) + single-wave grid
// via 2 rows/block -- but unlike R8, the two rows run as ONE continuous
// 40-slice cp.async pipeline: no mid-block drain, no mid-block syncs (R8's
// regression is attributed to exactly those). Per-row x per-warp histograms;
// warp-private zeroing removes the opening syncthreads. Mask is word-packed
// 0/1 (established R2+).
__global__ __launch_bounds__(256, 8)
void count_hist_kernel(const float* __restrict__ sim,
                       const uint4* __restrict__ mask,
                       float* __restrict__ out)
{
    __shared__ int   hist[RPB][CDIM][NWARP][32];  // 8KB; bin == bank
    __shared__ uint4 ring[NWARP][NSLOT][32];      // 20KB; 512B slices/warp

    const int t    = threadIdx.x;
    const int warp = t >> 5;
    const int lane = t & 31;
    const int bq0  = blockIdx.x * RPB;

    uint64_t pol;
    asm("createpolicy.fractional.L2::evict_first.b64 %0, 1.0;" : "=l"(pol));

    // warp-private zeroing: each warp only atomics into its own copies, so no
    // block sync is needed before the mainloop.
    #pragma unroll
    for (int r = 0; r < RPB; ++r)
        #pragma unroll
        for (int c = 0; c < CDIM; ++c)
            hist[r][c][warp][lane] = 0;

    // Per-row, per-thread global bases (16B vector units).
    const uint4*  gm[RPB];
    const float4* gs[RPB];
    #pragma unroll
    for (int r = 0; r < RPB; ++r) {
        const int bq = bq0 + r;
        const int b  = bq / QDIM;
        const int q  = bq - b * QDIM;
        gm[r] = mask + (size_t)bq * (DDIM / 4) + warp * 32 + lane;
        gs[r] = reinterpret_cast<const float4*>(sim)
                + ((size_t)b * CDIM * QDIM + q) * (DDIM / 4) + warp * 32 + lane;
    }
    const int cStride4 = QDIM * DDIM / 4;         // 32768

    const uint32_t rl =
        (uint32_t)__cvta_generic_to_shared(&ring[warp][0][lane]);

    // slice j (0..39): r = j/20, jj = j%20, it = jj/5, k = jj%5.
    // k==0 -> mask slice; k>=1 -> sim c=k-1. vec offset = it*256.
    // Prologue: slices 0..3 in flight (distance 4; slot j%5 is overwritten one
    // iteration after consumption -> no WAR hazard).
    #pragma unroll
    for (int j = 0; j < 4; ++j) {
        const int jj = j % NSLICE, it = jj / 5, k = jj % 5;
        const void* g = (k == 0)
            ? (const void*)(gm[j / NSLICE] + it * 256)
            : (const void*)(gs[j / NSLICE] + (k - 1) * cStride4 + it * 256);
        cp_async16_ef(rl + (j % NSLOT) * 512, g, pol);
        CP_COMMIT();
    }

    uint4 m;  // mask quad: loaded on k==0 slices, used by the next 4 sim slices

    #pragma unroll
    for (int j = 0; j < RPB * NSLICE; ++j) {
        // One trailing commit per iter (empty in the tail) keeps exactly 4
        // groups pending at every wait => constant CP_WAIT(3) retires slice j.
        CP_WAIT(3);

        const int r  = j / NSLICE;
        const int jj = j % NSLICE;

        if ((jj % 5) == 0) {
            m = ring[warp][j % NSLOT][lane];
        } else {
            const int c = (jj % 5) - 1;
            const float4 s =
                *reinterpret_cast<const float4*>(&ring[warp][j % NSLOT][lane]);
            // (int)((x+1.00001f)*14.0f) == trunc(((x+1.00001f)/2)*28) bit-exact
            const int b0 = (int)((s.x + 1.00001f) * 14.0f);
            const int b1 = (int)((s.y + 1.00001f) * 14.0f);
            const int b2 = (int)((s.z + 1.00001f) * 14.0f);
            const int b3 = (int)((s.w + 1.00001f) * 14.0f);
            if (m.x) atomicAdd(&hist[r][c][warp][b0], 1);
            if (m.y) atomicAdd(&hist[r][c][warp][b1], 1);
            if (m.z) atomicAdd(&hist[r][c][warp][b2], 1);
            if (m.w) atomicAdd(&hist[r][c][warp][b3], 1);
        }

        if (j + 4 < RPB * NSLICE) {
            const int jn = j + 4;
            const int jj2 = jn % NSLICE, it = jj2 / 5, k = jj2 % 5;
            const void* g = (k == 0)
                ? (const void*)(gm[jn / NSLICE] + it * 256)
                : (const void*)(gs[jn / NSLICE] + (k - 1) * cStride4 + it * 256);
            cp_async16_ef(rl + (jn % NSLOT) * 512, g, pol);
        }
        CP_COMMIT();
    }
    __syncthreads();

    // reduce 8 warp-copies for both rows: RPB*CDIM*NBINS = 232 outputs
    if (t < RPB * CDIM * NBINS) {
        const int r   = t / (CDIM * NBINS);
        const int rem = t - r * (CDIM * NBINS);
        const int c   = rem / NBINS;
        const int bin = rem - c * NBINS;
        const int bq  = bq0 + r;
        const int b   = bq / QDIM;
        const int q   = bq - b * QDIM;
        int sum = 0;
        #pragma unroll
        for (int w = 0; w < NWARP; ++w) sum += hist[r][c][w][bin];
        out[(((size_t)b * CDIM + c) * QDIM + q) * NBINS + bin] = (float)sum;
    }
}

extern "C" void kernel_launch(void* const* d_in, const int* in_sizes, int n_in,
                              void* d_out, int out_size)
{
    // sim is 4x larger (element count) than mask; pick by size for robustness.
    int i_sim  = 0, i_mask = 1;
    if (n_in >= 2 && in_sizes[1] > in_sizes[0]) { i_sim = 1; i_mask = 0; }

    const float* sim  = (const float*)d_in[i_sim];    // [B, C, Q, D] float32
    const uint4* mask = (const uint4*)d_in[i_mask];   // [B, Q, D] word-packed bool
    float*       out  = (float*)d_out;                // [B, C, Q, NBINS] float32

    const int rows   = in_sizes[i_mask] / DDIM;       // B*Q = 2048
    const int blocks = rows / RPB;                    // 1024 -> single wave

    count_hist_kernel<<<blocks, 256>>>(sim, mask, out);
}

// round 17
// speedup vs baseline: 1.0787x; 1.0787x over previous
#include <cuda_runtime.h>
#include <stdint.h>

#define NBINS 29
#define DDIM  4096
#define CDIM  4
#define QDIM  32
#define NWARP 8
#define NSLOT 6          // ring slots per warp (prefetch distance 5)
#define NSLICE 20        // per block: 4 iters x (1 mask + 4 sim) slices

// cp.async with an L2 evict-first hint: inputs are read-once (R15: +7% from
// marking the stream transient -- the one proven policy win).
__device__ __forceinline__ void cp_async16_ef(uint32_t saddr, const void* gaddr,
                                              uint64_t pol) {
    asm volatile("cp.async.cg.shared.global.L2::cache_hint [%0], [%1], 16, %2;\n"
                 :: "r"(saddr), "l"(gaddr), "l"(pol) : "memory");
}
#define CP_COMMIT() asm volatile("cp.async.commit_group;\n" ::: "memory")
#define CP_WAIT(N)  asm volatile("cp.async.wait_group %0;\n" :: "n"(N) : "memory")

// R15 structure (proven best: 29.06us kernel / 31.2 dur; grid 2048, cp.async
// ring, evict_first) with prefetch distance 4 -> 5 (NSLOT 6). Block-count axis
// is mapped (2048 beats 1024 twice: R8, R16); wave shaping, reg batching,
// split histograms, sequential streams all tested and lost. Mask is
// word-packed 0/1 (established R2+). Per-warp integer histograms in shared
// memory, reduced to float at the end.
__global__ __launch_bounds__(256, 8)
void count_hist_kernel(const float* __restrict__ sim,
                       const uint4* __restrict__ mask,
                       float* __restrict__ out)
{
    __shared__ int   hist[CDIM][NWARP][32];     // 4KB; bin == bank (29->32 pad)
    __shared__ uint4 ring[NWARP][NSLOT][32];    // 24KB; 512B slices, per-warp

    const int t    = threadIdx.x;
    const int warp = t >> 5;
    const int lane = t & 31;
    const int bq   = blockIdx.x;                // 0 .. B*Q-1
    const int b    = bq / QDIM;
    const int q    = bq - b * QDIM;

    uint64_t pol;
    asm("createpolicy.fractional.L2::evict_first.b64 %0, 1.0;" : "=l"(pol));

    #pragma unroll
    for (int i = t; i < CDIM * NWARP * 32; i += 256)
        (&hist[0][0][0])[i] = 0;
    __syncthreads();

    // Per-thread global bases (16B vector units), offset warp*32+lane.
    const uint4* __restrict__ gm =
        mask + (size_t)bq * (DDIM / 4) + warp * 32 + lane;
    const float4* __restrict__ gs =
        reinterpret_cast<const float4*>(sim + ((size_t)b * CDIM * QDIM + q) * DDIM)
        + warp * 32 + lane;
    const int cStride4 = QDIM * DDIM / 4;       // 32768

    const uint32_t rl =
        (uint32_t)__cvta_generic_to_shared(&ring[warp][0][lane]);

    // slice j (0..19): it = j/5, k = j%5. k==0 -> mask; k>=1 -> sim c=k-1.
    // Prologue: slices 0..4 in flight (distance 5; slot (j+5)%6 was consumed
    // at iteration j-1 -> no WAR hazard).
    #pragma unroll
    for (int j = 0; j < 5; ++j) {
        const int it = j / 5, k = j % 5;
        const void* g = (k == 0) ? (const void*)(gm + it * 256)
                                 : (const void*)(gs + (k - 1) * cStride4 + it * 256);
        cp_async16_ef(rl + (j % NSLOT) * 512, g, pol);
        CP_COMMIT();
    }

    uint4 m;  // mask quad for the current iter

    #pragma unroll
    for (int j = 0; j < NSLICE; ++j) {
        // One trailing commit per iter (empty in the tail) keeps exactly 5
        // groups pending at every wait => constant CP_WAIT(4) retires slice j.
        CP_WAIT(4);

        if ((j % 5) == 0) {
            m = ring[warp][j % NSLOT][lane];    // park mask in regs for 4 slices
        } else {
            const int c = (j % 5) - 1;
            const float4 s =
                *reinterpret_cast<const float4*>(&ring[warp][j % NSLOT][lane]);
            // (int)((x+1.00001f)*14.0f) == trunc(((x+1.00001f)/2)*28) bit-exact
            const int b0 = (int)((s.x + 1.00001f) * 14.0f);
            const int b1 = (int)((s.y + 1.00001f) * 14.0f);
            const int b2 = (int)((s.z + 1.00001f) * 14.0f);
            const int b3 = (int)((s.w + 1.00001f) * 14.0f);
            if (m.x) atomicAdd(&hist[c][warp][b0], 1);
            if (m.y) atomicAdd(&hist[c][warp][b1], 1);
            if (m.z) atomicAdd(&hist[c][warp][b2], 1);
            if (m.w) atomicAdd(&hist[c][warp][b3], 1);
        }

        // Issue slice j+5 into the slot freed at iteration j-1.
        if (j + 5 < NSLICE) {
            const int jn = j + 5;
            const int it = jn / 5, k = jn % 5;
            const void* g = (k == 0) ? (const void*)(gm + it * 256)
                                     : (const void*)(gs + (k - 1) * cStride4 + it * 256);
            cp_async16_ef(rl + (jn % NSLOT) * 512, g, pol);
        }
        CP_COMMIT();
    }
    __syncthreads();

    // reduce 8 warp-copies and write: C*NBINS = 116 outputs per block
    if (t < CDIM * NBINS) {
        const int c   = t / NBINS;
        const int bin = t - c * NBINS;
        int sum = 0;
        #pragma unroll
        for (int w = 0; w < NWARP; ++w) sum += hist[c][w][bin];
        out[(((size_t)b * CDIM + c) * QDIM + q) * NBINS + bin] = (float)sum;
    }
}

extern "C" void kernel_launch(void* const* d_in, const int* in_sizes, int n_in,
                              void* d_out, int out_size)
{
    // sim is 4x larger (element count) than mask; pick by size for robustness.
    int i_sim  = 0, i_mask = 1;
    if (n_in >= 2 && in_sizes[1] > in_sizes[0]) { i_sim = 1; i_mask = 0; }

    const float* sim  = (const float*)d_in[i_sim];    // [B, C, Q, D] float32
    const uint4* mask = (const uint4*)d_in[i_mask];   // [B, Q, D] word-packed bool
    float*       out  = (float*)d_out;                // [B, C, Q, NBINS] float32

    const int blocks = in_sizes[i_mask] / DDIM;       // B*Q = 2048

    count_hist_kernel<<<blocks, 256>>>(sim, mask, out);
}